// round 7
// baseline (speedup 1.0000x reference)
#include <cuda_runtime.h>
#include <cstdint>

#define N_NODES 50000
#define F_DIM 512
#define C_DIM 64
#define O_DIM 256
#define GRID_MAX 152
#define NT 128
#define NTILES ((N_NODES + NT - 1) / NT)   // 391
#define THREADS 1024

typedef unsigned long long ull;

// Scratch (static device arrays; no allocation)
__device__ float g_Mpart[GRID_MAX * C_DIM * F_DIM];   // per-block partial M = s^T x
__device__ float g_cspart[GRID_MAX * C_DIM];          // per-block partial colsum(s)
__device__ float g_M[C_DIM * F_DIM];
__device__ float g_cs[C_DIM];
__device__ float g_pooled[C_DIM * F_DIM];
__device__ unsigned g_bar;                            // monotonic grid barrier counter

static __device__ __forceinline__ ull pack2(float lo, float hi) {
    ull r; asm("mov.b64 %0, {%1,%2};" : "=l"(r) : "f"(lo), "f"(hi)); return r;
}
static __device__ __forceinline__ void unpack2(ull v, float& lo, float& hi) {
    asm("mov.b64 {%0,%1}, %2;" : "=f"(lo), "=f"(hi) : "l"(v));
}
static __device__ __forceinline__ ull fma2(ull a, ull b, ull c) {
    ull d; asm("fma.rn.f32x2 %0, %1, %2, %3;" : "=l"(d) : "l"(a), "l"(b), "l"(c)); return d;
}
static __device__ __forceinline__ void cp16(uint32_t dst, const void* src, int sz) {
    asm volatile("cp.async.cg.shared.global [%0], [%1], 16, %2;" :: "r"(dst), "l"(src), "r"(sz));
}
static __device__ __forceinline__ void cp_wait_all() {
    asm volatile("cp.async.wait_all;" ::: "memory");
}

// Grid-wide barrier: all CTAs resident (grid == #SMs, occ 1). Monotonic
// counter -> safe across graph replays.
static __device__ __forceinline__ void grid_sync() {
    __syncthreads();
    __threadfence();
    if (threadIdx.x == 0) {
        unsigned old = atomicAdd(&g_bar, 1u);
        unsigned target = old - (old % gridDim.x) + gridDim.x;
        while (*(volatile unsigned*)&g_bar < target) __nanosleep(64);
        __threadfence();
    }
    __syncthreads();
}

// Fused: logits -> softmax -> M += s^T x (persistent tiles), then grid-sync'd
// reduction + pooled = M@We + cs(x)be + out = pooled@Wo + bo.
// smem: Wp[512][64] (128KB) + x chunk row-major [128 n][128 f] (64KB)
//       + s [128][64] (32KB) + csum[64]
__global__ __launch_bounds__(THREADS, 1) void k1_fused(
    const float* __restrict__ x, const float* __restrict__ Wp, const float* __restrict__ bp,
    const float* __restrict__ We, const float* __restrict__ be,
    const float* __restrict__ Wo, const float* __restrict__ bo,
    float* __restrict__ out)
{
    extern __shared__ float sm[];
    float*  WpS = sm;                                 // 32768 floats
    float*  xsm = sm + 32768;                         // 16384 floats: [n][128] row-major
    float4* ss4 = (float4*)(sm + 32768 + 16384);      // 128 n x 16 float4
    float*  csS = sm + 32768 + 16384 + 8192;          // 64 floats

    const int tid = threadIdx.x;
    const uint32_t xsm_u = (uint32_t)__cvta_generic_to_shared(xsm);

    // Stage Wp once (global [512][64] row-major -> same layout in smem)
    {
        const float4* src = (const float4*)Wp;
        float4* dst = (float4*)WpS;
        #pragma unroll
        for (int it = 0; it < 8; ++it) dst[tid + it * THREADS] = src[tid + it * THREADS];
    }
    if (tid < 64) csS[tid] = 0.f;

    // Phase A/B ownership: 2 nodes x 4 clusters per thread
    const int cq = tid & 15, ng = tid >> 4, n0 = ng * 2;
    // Phase C ownership: 4 clusters x 2 features per thread (c-packed acc)
    const int cquad = tid >> 6;                       // 0..15 -> c0 = cquad*4
    const int fp    = tid & 63;                       // f-pair within kc chunk

    ull Macc[4][2][2];                                // [kc][fi][cpair]
    #pragma unroll
    for (int a = 0; a < 4; ++a)
        #pragma unroll
        for (int b = 0; b < 2; ++b) { Macc[a][b][0] = 0ull; Macc[a][b][1] = 0ull; }
    float cs0 = 0.f, cs1 = 0.f, cs2 = 0.f, cs3 = 0.f;

    for (int tile = blockIdx.x; tile < NTILES; tile += gridDim.x) {
        const int node0 = tile * NT;

        // ---------------- Phase A: logits = x @ Wp + bp ----------------
        ull acc[2][2];
        {
            const float4 bp4 = ((const float4*)bp)[cq];
            acc[0][0] = pack2(bp4.x, bp4.y); acc[0][1] = pack2(bp4.z, bp4.w);
            acc[1][0] = acc[0][0];           acc[1][1] = acc[0][1];
        }

        for (int kc = 0; kc < 4; ++kc) {
            __syncthreads();
            #pragma unroll
            for (int it = 0; it < 4; ++it) {
                int j = tid + it * THREADS;
                int f4 = j & 31, n = j >> 5;
                int node = node0 + n;
                int ok = node < N_NODES;
                const float* src = x + (size_t)(ok ? node : 0) * F_DIM + kc * 128 + f4 * 4;
                cp16(xsm_u + (uint32_t)(n * 128 + f4 * 4) * 4u, src, ok ? 16 : 0);
            }
            cp_wait_all();
            __syncthreads();

            const float4* xr = (const float4*)(xsm + n0 * 128);
            #pragma unroll 8
            for (int k4 = 0; k4 < 32; ++k4) {
                float4 xv0 = xr[k4];
                float4 xv1 = xr[32 + k4];
                #pragma unroll
                for (int j = 0; j < 4; ++j) {
                    ulonglong2 w2 = *(const ulonglong2*)(WpS + (kc * 128 + k4 * 4 + j) * 64 + cq * 4);
                    float a0 = (j == 0) ? xv0.x : (j == 1) ? xv0.y : (j == 2) ? xv0.z : xv0.w;
                    float a1 = (j == 0) ? xv1.x : (j == 1) ? xv1.y : (j == 2) ? xv1.z : xv1.w;
                    ull x0 = pack2(a0, a0), x1 = pack2(a1, a1);
                    acc[0][0] = fma2(w2.x, x0, acc[0][0]);
                    acc[0][1] = fma2(w2.y, x0, acc[0][1]);
                    acc[1][0] = fma2(w2.x, x1, acc[1][0]);
                    acc[1][1] = fma2(w2.y, x1, acc[1][1]);
                }
            }
        }

        // ---------------- Phase B: softmax over clusters ----------------
        #pragma unroll
        for (int i = 0; i < 2; ++i) {
            float l0, l1, l2, l3;
            unpack2(acc[i][0], l0, l1);
            unpack2(acc[i][1], l2, l3);
            float m = fmaxf(fmaxf(l0, l1), fmaxf(l2, l3));
            #pragma unroll
            for (int d = 1; d < 16; d <<= 1) m = fmaxf(m, __shfl_xor_sync(0xffffffffu, m, d));
            float e0 = __expf(l0 - m), e1 = __expf(l1 - m), e2 = __expf(l2 - m), e3 = __expf(l3 - m);
            float s = e0 + e1 + e2 + e3;
            #pragma unroll
            for (int d = 1; d < 16; d <<= 1) s += __shfl_xor_sync(0xffffffffu, s, d);
            float r = __frcp_rn(s);
            float4 sv = make_float4(e0 * r, e1 * r, e2 * r, e3 * r);
            if (node0 + n0 + i >= N_NODES) sv = make_float4(0.f, 0.f, 0.f, 0.f);
            cs0 += sv.x; cs1 += sv.y; cs2 += sv.z; cs3 += sv.w;
            ss4[(n0 + i) * 16 + cq] = sv;
        }

        // ------- Phase C: M[c][f] += s[n][c] * x[n][f]  (c-packed, 4c x 2f) -------
        #pragma unroll
        for (int kc = 0; kc < 4; ++kc) {
            __syncthreads();
            #pragma unroll
            for (int it = 0; it < 4; ++it) {
                int j = tid + it * THREADS;
                int f4 = j & 31, n = j >> 5;
                int node = node0 + n;
                int ok = node < N_NODES;
                const float* src = x + (size_t)(ok ? node : 0) * F_DIM + kc * 128 + f4 * 4;
                cp16(xsm_u + (uint32_t)(n * 128 + f4 * 4) * 4u, src, ok ? 16 : 0);
            }
            cp_wait_all();
            __syncthreads();

            const float2*     xp  = (const float2*)xsm + fp;
            const ulonglong2* ssp = (const ulonglong2*)ss4 + cquad;
            #pragma unroll 8
            for (int n = 0; n < NT; ++n) {
                ulonglong2 s2 = ssp[n * 16];          // (s_c0,s_c1),(s_c2,s_c3) broadcast
                float2 xf = xp[n * 64];               // LDS.64, contiguous per warp
                ull x0 = pack2(xf.x, xf.x), x1 = pack2(xf.y, xf.y);
                Macc[kc][0][0] = fma2(s2.x, x0, Macc[kc][0][0]);
                Macc[kc][0][1] = fma2(s2.y, x0, Macc[kc][0][1]);
                Macc[kc][1][0] = fma2(s2.x, x1, Macc[kc][1][0]);
                Macc[kc][1][1] = fma2(s2.y, x1, Macc[kc][1][1]);
            }
        }
    }

    // Write per-block partial M
    {
        const int c0 = cquad * 4;
        float* mp = g_Mpart + (size_t)blockIdx.x * (C_DIM * F_DIM);
        #pragma unroll
        for (int kc = 0; kc < 4; ++kc)
            #pragma unroll
            for (int fi = 0; fi < 2; ++fi)
                #pragma unroll
                for (int cp = 0; cp < 2; ++cp) {
                    float va, vb;
                    unpack2(Macc[kc][fi][cp], va, vb);
                    int f = kc * 128 + fp * 2 + fi;
                    mp[(c0 + 2 * cp + 0) * F_DIM + f] = va;
                    mp[(c0 + 2 * cp + 1) * F_DIM + f] = vb;
                }
    }

    // Per-block partial colsum(s)
    atomicAdd(&csS[cq * 4 + 0], cs0);
    atomicAdd(&csS[cq * 4 + 1], cs1);
    atomicAdd(&csS[cq * 4 + 2], cs2);
    atomicAdd(&csS[cq * 4 + 3], cs3);
    __syncthreads();
    if (tid < 64) g_cspart[blockIdx.x * 64 + tid] = csS[tid];

    // ================= In-kernel epilogue (grid-synchronized) =================
    const int G = gridDim.x;

    grid_sync();

    // Reduce partials: M (32768 outputs, coalesced; blocks 0..31) + cs (block 32)
    {
        unsigned idx = blockIdx.x * (unsigned)THREADS + (unsigned)tid;
        if (idx < C_DIM * F_DIM) {
            float s = 0.f;
            #pragma unroll 4
            for (int b = 0; b < G; ++b) s += g_Mpart[(size_t)b * (C_DIM * F_DIM) + idx];
            g_M[idx] = s;
        }
        if (blockIdx.x == 32 && tid < C_DIM) {
            float s = 0.f;
            #pragma unroll 4
            for (int b = 0; b < G; ++b) s += g_cspart[b * C_DIM + tid];
            g_cs[tid] = s;
        }
    }

    grid_sync();

    // pooled = M @ We + cs (x) be : blocks 0..15, each 4 clusters (2 per thread-half)
    if (blockIdx.x < 16) {
        const int f = tid & 511;
        const int c0 = blockIdx.x * 4 + (tid >> 9) * 2;
        const float bef = be[f];
        float a0 = g_cs[c0 + 0] * bef;
        float a1 = g_cs[c0 + 1] * bef;
        #pragma unroll 8
        for (int k = 0; k < F_DIM; ++k) {
            float wv = We[(size_t)k * F_DIM + f];     // coalesced
            a0 += g_M[(c0 + 0) * F_DIM + k] * wv;     // broadcast
            a1 += g_M[(c0 + 1) * F_DIM + k] * wv;
        }
        g_pooled[(c0 + 0) * F_DIM + f] = a0;
        g_pooled[(c0 + 1) * F_DIM + f] = a1;
    }

    grid_sync();

    // out = pooled @ Wo + bo : blocks 0..63 (one cluster each), k split 4 ways
    if (blockIdx.x < 64) {
        const int o = tid & 255, q = tid >> 8, c = blockIdx.x;
        float a = 0.f;
        const int kbeg = q * 128;
        #pragma unroll 8
        for (int k = kbeg; k < kbeg + 128; ++k)
            a += g_pooled[c * F_DIM + k] * Wo[(size_t)k * O_DIM + o];
        float* rsm = xsm;                              // reuse x staging area
        rsm[q * 256 + o] = a;
        __syncthreads();
        if (q == 0)
            out[c * O_DIM + o] = rsm[o] + rsm[256 + o] + rsm[512 + o] + rsm[768 + o] + bo[o];
    }
}

extern "C" void kernel_launch(void* const* d_in, const int* in_sizes, int n_in,
                              void* d_out, int out_size) {
    const float* x  = (const float*)d_in[0];
    // d_in[1] = edge_index (int64), d_in[2] = batch (int64): unused by the output
    const float* Wp = (const float*)d_in[3];
    const float* bp = (const float*)d_in[4];
    const float* We = (const float*)d_in[5];
    const float* be = (const float*)d_in[6];
    const float* Wo = (const float*)d_in[7];
    const float* bo = (const float*)d_in[8];
    float* out = (float*)d_out;

    int dev = 0;
    cudaGetDevice(&dev);
    int smc = GRID_MAX;
    cudaDeviceGetAttribute(&smc, cudaDevAttrMultiProcessorCount, dev);
    int G = smc < GRID_MAX ? smc : GRID_MAX;

    const int SMEM1 = (32768 + 16384 + 8192 + 64) * (int)sizeof(float);  // 229632 B
    cudaFuncSetAttribute(k1_fused, cudaFuncAttributeMaxDynamicSharedMemorySize, SMEM1);

    k1_fused<<<G, THREADS, SMEM1>>>(x, Wp, bp, We, be, Wo, bo, out);
}